// round 4
// baseline (speedup 1.0000x reference)
#include <cuda_runtime.h>
#include <cuda_bf16.h>
#include <cstdint>

// ---------------- problem constants ----------------
#define BB      8          // batch
#define LL      1048576    // sequence length
#define KW      500        // conv kernel == stride
#define CIN     8
#define COUT    128
#define VOCAB   257
#define TT      2097       // (LL-KW)/KW + 1
#define MM      (BB*TT)    // 16776 windows
#define NN      256        // 2 convs * 128 channels, interleaved
#define KRED    4000       // KW * CIN

// ---------------- GEMM tiling ----------------
#define BM      128
#define BK      32         // 4 byte-positions * 8 emb dims per iter
#define ITERS   (KRED/BK)  // 125
#define NTHREADS 512

#define SA_STRIDE 40       // bf16 elems per A row (32 + 8 pad) -> 80B
#define SB_STRIDE 264      // bf16 elems per B row (256 + 8 pad) -> 528B

// ---------------- device scratch (static, no allocs) ----------------
__device__ __align__(16) __nv_bfloat16 g_Bmat[KRED * NN];   // 2 MB, L2-resident
__device__ __align__(16) __nv_bfloat16 g_emb[VOCAB * CIN];  // 4112 B
__device__ int g_pool[BB * COUT];                           // float bits, >=0

// ---------------- prep: weight repack fp32 -> bf16 interleaved ----------------
__global__ void prep_weights(const float* __restrict__ w1,
                             const float* __restrict__ w2) {
    int idx = blockIdx.x * blockDim.x + threadIdx.x;   // over COUT*CIN*KW = 512000
    if (idx >= COUT * CIN * KW) return;
    int o    = idx / (CIN * KW);
    int rest = idx - o * (CIN * KW);
    int e    = rest / KW;
    int k    = rest - e * KW;
    __nv_bfloat162 v;
    v.x = __float2bfloat16(w1[idx]);   // even col  = conv1
    v.y = __float2bfloat16(w2[idx]);   // odd col   = conv2
    *reinterpret_cast<__nv_bfloat162*>(&g_Bmat[(k * CIN + e) * NN + 2 * o]) = v;
}

__global__ void prep_misc(const float* __restrict__ emb) {
    int tid = threadIdx.x;             // 1 block, 1024 threads
    for (int i = tid; i < VOCAB * CIN; i += 1024)
        g_emb[i] = __float2bfloat16(emb[i]);
    if (tid < BB * COUT) g_pool[tid] = 0;   // 0 bits == 0.0f, gated >= 0
}

// ---------------- helpers ----------------
__device__ __forceinline__ uint32_t smem_u32(const void* p) {
    return (uint32_t)__cvta_generic_to_shared(p);
}

__device__ __forceinline__ void ldmatrix_x4(uint32_t& r0, uint32_t& r1,
                                            uint32_t& r2, uint32_t& r3,
                                            uint32_t addr) {
    asm volatile("ldmatrix.sync.aligned.m8n8.x4.shared.b16 {%0,%1,%2,%3}, [%4];"
                 : "=r"(r0), "=r"(r1), "=r"(r2), "=r"(r3) : "r"(addr));
}

__device__ __forceinline__ void ldmatrix_x4_trans(uint32_t& r0, uint32_t& r1,
                                                  uint32_t& r2, uint32_t& r3,
                                                  uint32_t addr) {
    asm volatile("ldmatrix.sync.aligned.m8n8.x4.trans.shared.b16 {%0,%1,%2,%3}, [%4];"
                 : "=r"(r0), "=r"(r1), "=r"(r2), "=r"(r3) : "r"(addr));
}

__device__ __forceinline__ void mma_bf16(float* d, uint32_t a0, uint32_t a1,
                                         uint32_t a2, uint32_t a3,
                                         uint32_t b0, uint32_t b1) {
    asm volatile(
        "mma.sync.aligned.m16n8k16.row.col.f32.bf16.bf16.f32 "
        "{%0,%1,%2,%3}, {%4,%5,%6,%7}, {%8,%9}, {%0,%1,%2,%3};"
        : "+f"(d[0]), "+f"(d[1]), "+f"(d[2]), "+f"(d[3])
        : "r"(a0), "r"(a1), "r"(a2), "r"(a3), "r"(b0), "r"(b1));
}

// ---------------- main fused kernel: gather + GEMM + gate + maxpool ----------------
__global__ __launch_bounds__(NTHREADS, 1)
void malconv_main(const int* __restrict__ x,
                  const float* __restrict__ b1,
                  const float* __restrict__ b2) {
    __shared__ __align__(16) __nv_bfloat16 sEmb[VOCAB * CIN];     // 4112 B
    __shared__ __align__(16) __nv_bfloat16 sA[BM * SA_STRIDE];    // 10240 B
    __shared__ __align__(16) __nv_bfloat16 sB[BK * SB_STRIDE];    // 16896 B

    const int tid  = threadIdx.x;
    const int lane = tid & 31;
    const int warp = tid >> 5;
    const int wm   = warp >> 1;   // 0..7  -> rows wm*16..+16
    const int wn   = warp & 1;    // 0..1  -> cols wn*128..+128

    // cooperative copy of embedding table (257 rows of 16B)
    for (int i = tid; i < VOCAB; i += NTHREADS)
        reinterpret_cast<int4*>(sEmb)[i] = reinterpret_cast<const int4*>(g_emb)[i];

    const int m0 = blockIdx.x * BM;

    // per-thread A-gather coordinates: row r, byte-position-in-chunk kp
    const int r  = tid >> 2;
    const int kp = tid & 3;
    int m  = m0 + r;
    int mc = (m < MM) ? m : (MM - 1);        // clamp: garbage rows ignored later
    int bb = mc / TT;
    int tt = mc - bb * TT;
    const int* xptr = x + (size_t)bb * LL + (size_t)tt * KW + kp;

    // B prefetch coordinates: 1024 int4 per tile, 2 per thread
    const int4* gB4 = reinterpret_cast<const int4*>(g_Bmat);  // 32 int4 per row
    const int e0 = tid;
    const int e1 = tid + NTHREADS;
    const int row0 = e0 >> 5, c0 = e0 & 31;
    const int row1 = e1 >> 5, c1 = e1 & 31;

    // prefetch iteration 0
    int  xv  = xptr[0];
    int4 bv0 = gB4[e0];
    int4 bv1 = gB4[e1];

    float acc[16][4];
#pragma unroll
    for (int i = 0; i < 16; i++)
#pragma unroll
        for (int j = 0; j < 4; j++) acc[i][j] = 0.f;

    for (int kc = 0; kc < ITERS; kc++) {
        __syncthreads();   // previous compute done; also orders sEmb copy (iter 0)
        // ---- store staged tile to smem ----
        int4 ev = reinterpret_cast<const int4*>(sEmb)[xv];   // one emb row (8 bf16)
        *reinterpret_cast<int4*>(&sA[r * SA_STRIDE + kp * 8]) = ev;
        *reinterpret_cast<int4*>(&sB[row0 * SB_STRIDE + c0 * 8]) = bv0;
        *reinterpret_cast<int4*>(&sB[row1 * SB_STRIDE + c1 * 8]) = bv1;
        __syncthreads();
        // ---- prefetch next tile into registers (overlaps with MMA) ----
        if (kc + 1 < ITERS) {
            xv  = xptr[(kc + 1) * 4];
            bv0 = gB4[(kc + 1) * 1024 + e0];
            bv1 = gB4[(kc + 1) * 1024 + e1];
        }
        // ---- compute 128x256x32 ----
#pragma unroll
        for (int kk = 0; kk < 2; kk++) {
            uint32_t a0, a1, a2, a3;
            uint32_t aaddr = smem_u32(&sA[(wm * 16 + (lane & 15)) * SA_STRIDE +
                                          kk * 16 + (lane >> 4) * 8]);
            ldmatrix_x4(a0, a1, a2, a3, aaddr);
#pragma unroll
            for (int nt2 = 0; nt2 < 8; nt2++) {          // pairs of 8-col tiles
                int nb = wn * 128 + nt2 * 16;
                uint32_t b0, b1r, b2r, b3;
                uint32_t baddr = smem_u32(&sB[(kk * 16 + (lane & 15)) * SB_STRIDE +
                                              nb + (lane >> 4) * 8]);
                ldmatrix_x4_trans(b0, b1r, b2r, b3, baddr);
                mma_bf16(acc[nt2 * 2],     a0, a1, a2, a3, b0,  b1r);
                mma_bf16(acc[nt2 * 2 + 1], a0, a1, a2, a3, b2r, b3);
            }
        }
    }

    // ---- epilogue: bias + relu*sigmoid gate + global maxpool via atomicMax ----
    const int rbase = m0 + wm * 16 + (lane >> 2);
#pragma unroll
    for (int nt = 0; nt < 16; nt++) {
        int o = wn * 64 + nt * 4 + (lane & 3);   // output channel (pair col / 2)
        float bias1 = __ldg(&b1[o]);
        float bias2 = __ldg(&b2[o]);
#pragma unroll
        for (int h = 0; h < 2; h++) {
            int mrow = rbase + h * 8;
            if (mrow < MM) {
                float c1v = acc[nt][h * 2]     + bias1;   // even col = conv1
                float c2v = acc[nt][h * 2 + 1] + bias2;   // odd col  = conv2
                float g = fmaxf(c1v, 0.f) * (1.f / (1.f + __expf(-c2v)));
                int bidx = mrow / TT;
                atomicMax(&g_pool[bidx * COUT + o], __float_as_int(g));
            }
        }
    }
}

// ---------------- dense head: 128->128 relu, 128->1 sigmoid ----------------
__global__ void final_dense(const float* __restrict__ wd1,
                            const float* __restrict__ bd1,
                            const float* __restrict__ wd2,
                            const float* __restrict__ bd2,
                            float* __restrict__ out) {
    __shared__ float sp[COUT];
    __shared__ float red[COUT];
    int tid = threadIdx.x;   // 128 threads
    for (int b = 0; b < BB; b++) {
        sp[tid] = __int_as_float(g_pool[b * COUT + tid]);
        __syncthreads();
        float a = bd1[tid];
#pragma unroll
        for (int i = 0; i < COUT; i++) a += sp[i] * wd1[tid * COUT + i];
        float h = fmaxf(a, 0.f);
        red[tid] = h * wd2[tid];
        __syncthreads();
        for (int s = 64; s > 0; s >>= 1) {
            if (tid < s) red[tid] += red[tid + s];
            __syncthreads();
        }
        if (tid == 0) out[b] = 1.f / (1.f + expf(-(red[0] + bd2[0])));
        __syncthreads();
    }
}

// ---------------- launch ----------------
extern "C" void kernel_launch(void* const* d_in, const int* in_sizes, int n_in,
                              void* d_out, int out_size) {
    const int*   x   = (const int*)  d_in[0];
    const float* emb = (const float*)d_in[1];
    const float* w1  = (const float*)d_in[2];
    const float* b1  = (const float*)d_in[3];
    const float* w2  = (const float*)d_in[4];
    const float* b2  = (const float*)d_in[5];
    const float* wd1 = (const float*)d_in[6];
    const float* bd1 = (const float*)d_in[7];
    const float* wd2 = (const float*)d_in[8];
    const float* bd2 = (const float*)d_in[9];
    float* out = (float*)d_out;

    prep_weights<<<(COUT * CIN * KW + 511) / 512, 512>>>(w1, w2);
    prep_misc<<<1, 1024>>>(emb);
    malconv_main<<<(MM + BM - 1) / BM, NTHREADS>>>(x, b1, b2);
    final_dense<<<1, COUT>>>(wd1, bd1, wd2, bd2, out);
}

// round 9
// speedup vs baseline: 1.7554x; 1.7554x over previous
#include <cuda_runtime.h>
#include <cuda_bf16.h>
#include <cstdint>

// ---------------- problem constants ----------------
#define BB      8          // batch
#define LL      1048576    // sequence length
#define KW      500        // conv kernel == stride
#define CIN     8
#define COUT    128
#define VOCAB   257
#define TT      2097       // (LL-KW)/KW + 1
#define MM      (BB*TT)    // 16776 windows
#define NN      256        // 2 convs * 128 channels interleaved (even=conv1)
#define KRED    4000       // KW * CIN

// ---------------- GEMM tiling ----------------
#define BM      128
#define BK      32         // 4 byte-positions * 8 emb dims per iter
#define ITERS   (KRED/BK)  // 125 (125*4 = 500 positions, exact)
#define NTHREADS 512
#define NBLK    ((MM + BM - 1) / BM)   // 132
#define DEPTH   4          // cp.async pipeline stages

#define SA_STRIDE 40       // bf16 elems per A row (32 + 8 pad) -> 80B
#define SB_STRIDE 264      // bf16 elems per B row (256 + 8 pad) -> 528B
#define SA_STAGE  (BM * SA_STRIDE * 2)   // 10240 B
#define SB_STAGE  (BK * SB_STRIDE * 2)   // 16896 B

// dynamic smem layout (bytes)
#define SM_A      0
#define SM_B      (DEPTH * SA_STAGE)                 // 40960
#define SM_POOL   (SM_B + DEPTH * SB_STAGE)          // 108544
#define SMEM_BYTES (SM_POOL + 2 * COUT * 4)          // 109568

// ---------------- device scratch (static, no allocs) ----------------
__device__ __align__(16) __nv_bfloat16 g_Bmat[KRED * NN];   // 2 MB, K-major
__device__ __align__(16) __nv_bfloat16 g_emb[VOCAB * CIN];  // 4112 B
__device__ int g_pool[BB * COUT];                           // float bits, >=0

// ---------------- prep kernels ----------------
__global__ void prep_weights(const float* __restrict__ w1,
                             const float* __restrict__ w2) {
    int idx = blockIdx.x * blockDim.x + threadIdx.x;   // over COUT*CIN*KW = 512000
    if (idx >= COUT * CIN * KW) return;
    int o    = idx / (CIN * KW);
    int rest = idx - o * (CIN * KW);
    int e    = rest / KW;
    int k    = rest - e * KW;
    __nv_bfloat162 v;
    v.x = __float2bfloat16(w1[idx]);   // even col  = conv1
    v.y = __float2bfloat16(w2[idx]);   // odd col   = conv2
    *reinterpret_cast<__nv_bfloat162*>(&g_Bmat[(k * CIN + e) * NN + 2 * o]) = v;
}

__global__ void prep_misc(const float* __restrict__ emb) {
    int tid = threadIdx.x;             // 1 block, 1024 threads
    for (int i = tid; i < VOCAB * CIN; i += 1024)
        g_emb[i] = __float2bfloat16(emb[i]);
    if (tid < BB * COUT) g_pool[tid] = 0;   // 0 bits == 0.0f; gated >= 0
}

// ---------------- PTX helpers (sm_80-era only: valid on base sm_103) -------
__device__ __forceinline__ uint32_t smem_u32(const void* p) {
    return (uint32_t)__cvta_generic_to_shared(p);
}
__device__ __forceinline__ void cp16_ca(uint32_t dst, const void* src) {
    asm volatile("cp.async.ca.shared.global [%0], [%1], 16;" :: "r"(dst), "l"(src));
}
__device__ __forceinline__ void cp16_cg(uint32_t dst, const void* src) {
    asm volatile("cp.async.cg.shared.global [%0], [%1], 16;" :: "r"(dst), "l"(src));
}
__device__ __forceinline__ void cp_commit() {
    asm volatile("cp.async.commit_group;" ::: "memory");
}
template <int N>
__device__ __forceinline__ void cp_wait() {
    asm volatile("cp.async.wait_group %0;" :: "n"(N) : "memory");
}
__device__ __forceinline__ void ldmatrix_x4(uint32_t& r0, uint32_t& r1,
                                            uint32_t& r2, uint32_t& r3,
                                            uint32_t addr) {
    asm volatile("ldmatrix.sync.aligned.m8n8.x4.shared.b16 {%0,%1,%2,%3}, [%4];"
                 : "=r"(r0), "=r"(r1), "=r"(r2), "=r"(r3) : "r"(addr));
}
__device__ __forceinline__ void ldmatrix_x4_trans(uint32_t& r0, uint32_t& r1,
                                                  uint32_t& r2, uint32_t& r3,
                                                  uint32_t addr) {
    asm volatile("ldmatrix.sync.aligned.m8n8.x4.trans.shared.b16 {%0,%1,%2,%3}, [%4];"
                 : "=r"(r0), "=r"(r1), "=r"(r2), "=r"(r3) : "r"(addr));
}
__device__ __forceinline__ void mma_bf16(float* d, uint32_t a0, uint32_t a1,
                                         uint32_t a2, uint32_t a3,
                                         uint32_t b0, uint32_t b1) {
    asm volatile(
        "mma.sync.aligned.m16n8k16.row.col.f32.bf16.bf16.f32 "
        "{%0,%1,%2,%3}, {%4,%5,%6,%7}, {%8,%9}, {%0,%1,%2,%3};"
        : "+f"(d[0]), "+f"(d[1]), "+f"(d[2]), "+f"(d[3])
        : "r"(a0), "r"(a1), "r"(a2), "r"(a3), "r"(b0), "r"(b1));
}

// ---------------- main fused kernel: gather + GEMM + gate + maxpool --------
__global__ __launch_bounds__(NTHREADS, 1)
void malconv_main(const int* __restrict__ x,
                  const float* __restrict__ b1,
                  const float* __restrict__ b2) {
    extern __shared__ char smem[];
    const uint32_t sbase = smem_u32(smem);
    int* spool = (int*)(smem + SM_POOL);

    const int tid  = threadIdx.x;
    const int lane = tid & 31;
    const int warp = tid >> 5;
    const int wm   = warp >> 1;   // 0..7  -> rows wm*16..+16
    const int wn   = warp & 1;    // 0..1  -> cols wn*128..+128

    if (tid < 2 * COUT) spool[tid] = 0;

    const int m0   = blockIdx.x * BM;
    const int b_lo = m0 / TT;
    // fast path: whole CTA inside one batch and fully in range
    const bool fastpath = (m0 + BM - 1 < MM) && (b_lo == (m0 + BM - 1) / TT);

    // A-gather coords: thread -> (row r, byte-position-in-chunk kp)
    const int r  = tid >> 2;
    const int kp = tid & 3;
    int mc = min(m0 + r, MM - 1);        // clamp: garbage rows masked in epilogue
    int bb = mc / TT;
    int tt = mc - bb * TT;
    const int* xptr = x + (size_t)bb * LL + (size_t)tt * KW + kp;

    // B tile coords: 1024 int4 per stage, 2 per thread
    const char* bmat = (const char*)g_Bmat;          // row = 512B
    const int e0 = tid,        row0 = e0 >> 5, c0 = e0 & 31;
    const int e1 = tid + 512,  row1 = e1 >> 5, c1 = e1 & 31;

    const __nv_bfloat16* embp = g_emb;

    // ---- stage-fill lambda (all cp.async) ----
    auto fill = [&](int kc, int xv) {
        const int s = kc & (DEPTH - 1);
        const uint32_t aOff = sbase + SM_A + s * SA_STAGE;
        const uint32_t bOff = sbase + SM_B + s * SB_STAGE;
        cp16_ca(aOff + (r * SA_STRIDE + kp * 8) * 2, embp + xv * CIN);
        cp16_cg(bOff + (row0 * SB_STRIDE + c0 * 8) * 2,
                bmat + (size_t)(kc * BK + row0) * 512 + c0 * 16);
        cp16_cg(bOff + (row1 * SB_STRIDE + c1 * 8) * 2,
                bmat + (size_t)(kc * BK + row1) * 512 + c1 * 16);
    };

    // ---- prologue: fill stages 0..2 ----
    int xv0 = xptr[0], xv1 = xptr[4], xv2 = xptr[8];
    fill(0, xv0); cp_commit();
    fill(1, xv1); cp_commit();
    fill(2, xv2); cp_commit();
    int xreg = xptr[12];                 // x for stage 3

    float acc[16][4];
#pragma unroll
    for (int i = 0; i < 16; i++)
#pragma unroll
        for (int j = 0; j < 4; j++) acc[i][j] = 0.f;

    for (int kc = 0; kc < ITERS; kc++) {
        cp_wait<2>();          // stage kc landed (for this thread)
        __syncthreads();       // all threads' stage-kc data visible; stage kc-1 reads done
        if (kc + 3 < ITERS) fill(kc + 3, xreg);
        cp_commit();           // always commit to keep group arithmetic fixed
        if (kc + 4 < ITERS) xreg = xptr[(kc + 4) * 4];   // hidden under compute

        const uint32_t aOff = sbase + SM_A + (kc & (DEPTH - 1)) * SA_STAGE;
        const uint32_t bOff = sbase + SM_B + (kc & (DEPTH - 1)) * SB_STAGE;
#pragma unroll
        for (int kk = 0; kk < 2; kk++) {
            uint32_t a0, a1, a2, a3;
            uint32_t aaddr = aOff + ((wm * 16 + (lane & 15)) * SA_STRIDE +
                                     kk * 16 + (lane >> 4) * 8) * 2;
            ldmatrix_x4(a0, a1, a2, a3, aaddr);
#pragma unroll
            for (int nt2 = 0; nt2 < 8; nt2++) {          // pairs of 8-col tiles
                int nb = wn * 128 + nt2 * 16;
                uint32_t b0, b1r, b2r, b3;
                uint32_t baddr = bOff + ((kk * 16 + (lane & 15)) * SB_STRIDE +
                                         nb + (lane >> 4) * 8) * 2;
                ldmatrix_x4_trans(b0, b1r, b2r, b3, baddr);
                mma_bf16(acc[nt2 * 2],     a0, a1, a2, a3, b0,  b1r);
                mma_bf16(acc[nt2 * 2 + 1], a0, a1, a2, a3, b2r, b3);
            }
        }
    }
    __syncthreads();   // spool init + compute done before epilogue atomics

    // ---- epilogue: bias + relu*sigmoid gate + maxpool ----
    // thread holds rows rbase, rbase+8; channel o = wn*64 + nt*4 + (lane&3)
    const int rbase = m0 + wm * 16 + (lane >> 2);
    if (fastpath) {
        // warp-level max over the 8 row-groups (lane bits 2..4), then 4 lanes
        // per warp push 1 smem atomic per nt (distinct addresses)
#pragma unroll
        for (int nt = 0; nt < 16; nt++) {
            int o = wn * 64 + nt * 4 + (lane & 3);
            float bias1 = __ldg(&b1[o]);
            float bias2 = __ldg(&b2[o]);
            float gmax = -1.f;
#pragma unroll
            for (int h = 0; h < 2; h++) {
                float c1v = acc[nt][h * 2]     + bias1;   // even col = conv1
                float c2v = acc[nt][h * 2 + 1] + bias2;   // odd col  = conv2
                float g = fmaxf(c1v, 0.f) * (1.f / (1.f + __expf(-c2v)));
                gmax = fmaxf(gmax, g);
            }
#pragma unroll
            for (int off = 4; off < 32; off <<= 1)
                gmax = fmaxf(gmax, __shfl_xor_sync(0xFFFFFFFFu, gmax, off));
            if ((lane >> 2) == 0)
                atomicMax(&spool[o], __float_as_int(gmax));
        }
    } else {
        // boundary / tail CTAs: per-value smem atomics with row masking
#pragma unroll
        for (int nt = 0; nt < 16; nt++) {
            int o = wn * 64 + nt * 4 + (lane & 3);
            float bias1 = __ldg(&b1[o]);
            float bias2 = __ldg(&b2[o]);
#pragma unroll
            for (int h = 0; h < 2; h++) {
                int mrow = rbase + h * 8;
                if (mrow < MM) {
                    float c1v = acc[nt][h * 2]     + bias1;
                    float c2v = acc[nt][h * 2 + 1] + bias2;
                    float g = fmaxf(c1v, 0.f) * (1.f / (1.f + __expf(-c2v)));
                    int slot = mrow / TT - b_lo;          // 0 or 1
                    atomicMax(&spool[slot * COUT + o], __float_as_int(g));
                }
            }
        }
    }
    __syncthreads();
    if (tid < 2 * COUT) {
        int slot = tid >> 7, o = tid & (COUT - 1);
        int bidx = b_lo + slot;
        int v = spool[tid];
        if (bidx < BB && v != 0) atomicMax(&g_pool[bidx * COUT + o], v);
    }
}

// ---------------- dense head: one block per batch, latency-parallel --------
__global__ void final_dense(const float* __restrict__ wd1,
                            const float* __restrict__ bd1,
                            const float* __restrict__ wd2,
                            const float* __restrict__ bd2,
                            float* __restrict__ out) {
    __shared__ float sp[COUT];
    __shared__ float red[COUT];
    const int b = blockIdx.x;       // 8 blocks
    const int t = threadIdx.x;      // 128 threads: one hidden unit each
    sp[t] = __int_as_float(g_pool[b * COUT + t]);
    __syncthreads();
    const float4* wrow = (const float4*)(wd1 + t * COUT);
    float acc = bd1[t];
#pragma unroll
    for (int i = 0; i < COUT / 4; i++) {    // 32 independent LDG.128 in flight
        float4 w = wrow[i];
        acc += w.x * sp[4 * i] + w.y * sp[4 * i + 1] +
               w.z * sp[4 * i + 2] + w.w * sp[4 * i + 3];
    }
    red[t] = fmaxf(acc, 0.f) * wd2[t];
    __syncthreads();
    for (int s = 64; s > 0; s >>= 1) {
        if (t < s) red[t] += red[t + s];
        __syncthreads();
    }
    if (t == 0) out[b] = 1.f / (1.f + expf(-(red[0] + bd2[0])));
}

// ---------------- launch ----------------
extern "C" void kernel_launch(void* const* d_in, const int* in_sizes, int n_in,
                              void* d_out, int out_size) {
    const int*   x   = (const int*)  d_in[0];
    const float* emb = (const float*)d_in[1];
    const float* w1  = (const float*)d_in[2];
    const float* b1  = (const float*)d_in[3];
    const float* w2  = (const float*)d_in[4];
    const float* b2  = (const float*)d_in[5];
    const float* wd1 = (const float*)d_in[6];
    const float* bd1 = (const float*)d_in[7];
    const float* wd2 = (const float*)d_in[8];
    const float* bd2 = (const float*)d_in[9];
    float* out = (float*)d_out;

    cudaFuncSetAttribute(malconv_main, cudaFuncAttributeMaxDynamicSharedMemorySize,
                         SMEM_BYTES);
    prep_weights<<<(COUT * CIN * KW + 511) / 512, 512>>>(w1, w2);
    prep_misc<<<1, 1024>>>(emb);
    malconv_main<<<NBLK, NTHREADS, SMEM_BYTES>>>(x, b1, b2);
    final_dense<<<BB, COUT>>>(wd1, bd1, wd2, bd2, out);
}